// round 1
// baseline (speedup 1.0000x reference)
#include <cuda_runtime.h>

#define T_STEPS 512
#define BATCH   1024
#define IND     64
#define HID     8

// 84 MB scratch for the x-dependent precompute: [T][B][40] with
// slot q*8+j : q in {0..3}=gates f,i,u,o (x@Wq + bq + th_q), q=4: s = 0.5*(bh2k-bi2k-x@Wi2k)
__device__ __align__(16) float  g_P[(size_t)T_STEPS * BATCH * 40];
__device__ __align__(16) float2 g_wdup[64 * 40];
__device__ float g_bias[40];

// ---------------------------------------------------------------------------
// Stage: build fused [64 x 40] weight matrix (duplicated for f32x2) + bias row
// ---------------------------------------------------------------------------
__global__ void stage_kernel(const float* __restrict__ Wf, const float* __restrict__ bf, const float* __restrict__ thf,
                             const float* __restrict__ Wi, const float* __restrict__ bi, const float* __restrict__ thi,
                             const float* __restrict__ Wu, const float* __restrict__ bu, const float* __restrict__ thu,
                             const float* __restrict__ Wo, const float* __restrict__ bo, const float* __restrict__ tho,
                             const float* __restrict__ Wh2k, const float* __restrict__ bh2k,
                             const float* __restrict__ Wi2k, const float* __restrict__ bi2k)
{
    int idx = blockIdx.x * blockDim.x + threadIdx.x;
    if (idx < 64 * 40) {
        int k = idx / 40, c = idx - k * 40, q = c >> 3, j = c & 7;
        float wv;
        if (q == 0)      wv = Wf[k * 8 + j];
        else if (q == 1) wv = Wi[k * 8 + j];
        else if (q == 2) wv = Wu[k * 8 + j];
        else if (q == 3) wv = Wo[k * 8 + j];
        else             wv = -0.5f * Wi2k[k * 8 + j];
        g_wdup[idx] = make_float2(wv, wv);
    }
    if (idx < 40) {
        int q = idx >> 3, j = idx & 7;
        float bv;
        if (q == 0)      bv = bf[j] + thf[j];
        else if (q == 1) bv = bi[j] + thi[j];
        else if (q == 2) bv = bu[j] + thu[j];
        else if (q == 3) bv = bo[j] + tho[j];
        else             bv = 0.5f * (bh2k[j] - bi2k[j]);
        g_bias[idx] = bv;
    }
}

// ---------------------------------------------------------------------------
// f32x2 packed-FMA helpers (Blackwell)
// ---------------------------------------------------------------------------
__device__ __forceinline__ unsigned long long pk2(float lo, float hi) {
    unsigned long long r;
    asm("mov.b64 %0, {%1, %2};" : "=l"(r) : "f"(lo), "f"(hi));
    return r;
}
__device__ __forceinline__ unsigned long long fma2(unsigned long long a, unsigned long long b, unsigned long long c) {
    unsigned long long d;
    asm("fma.rn.f32x2 %0, %1, %2, %3;" : "=l"(d) : "l"(a), "l"(b), "l"(c));
    return d;
}
__device__ __forceinline__ void upk2(unsigned long long v, float& lo, float& hi) {
    asm("mov.b64 {%0, %1}, %2;" : "=f"(lo), "=f"(hi) : "l"(v));
}

// ---------------------------------------------------------------------------
// xproj: P[r][c] = sum_k X[r][k] * Wmat[k][c] + bias[c],  r = t*B+b
// 2 rows per thread via f32x2.  512 rows / block of 256 threads.
// ---------------------------------------------------------------------------
__global__ void __launch_bounds__(256) xproj_kernel(const float* __restrict__ X)
{
    __shared__ unsigned long long ws[64 * 40];
    int tid = threadIdx.x;
    const unsigned long long* wsrc = reinterpret_cast<const unsigned long long*>(g_wdup);
    #pragma unroll
    for (int i = 0; i < 10; i++) ws[tid + 256 * i] = wsrc[tid + 256 * i];
    __syncthreads();

    size_t rA = (size_t)blockIdx.x * 512 + tid;
    size_t rB = rA + 256;

    unsigned long long acc[40];
    #pragma unroll
    for (int c = 0; c < 40; c++) { float bv = g_bias[c]; acc[c] = pk2(bv, bv); }

    const float4* xa = reinterpret_cast<const float4*>(X + rA * IND);
    const float4* xb = reinterpret_cast<const float4*>(X + rB * IND);

    #pragma unroll 4
    for (int k4 = 0; k4 < 16; k4++) {
        float4 a = xa[k4], b2 = xb[k4];
        unsigned long long p0 = pk2(a.x, b2.x), p1 = pk2(a.y, b2.y),
                           p2 = pk2(a.z, b2.z), p3 = pk2(a.w, b2.w);
        int kb = k4 * 4;
        #pragma unroll
        for (int c = 0; c < 40; c++) acc[c] = fma2(p0, ws[(kb + 0) * 40 + c], acc[c]);
        #pragma unroll
        for (int c = 0; c < 40; c++) acc[c] = fma2(p1, ws[(kb + 1) * 40 + c], acc[c]);
        #pragma unroll
        for (int c = 0; c < 40; c++) acc[c] = fma2(p2, ws[(kb + 2) * 40 + c], acc[c]);
        #pragma unroll
        for (int c = 0; c < 40; c++) acc[c] = fma2(p3, ws[(kb + 3) * 40 + c], acc[c]);
    }

    float* pA = g_P + rA * 40;
    float* pB = g_P + rB * 40;
    #pragma unroll
    for (int c4 = 0; c4 < 10; c4++) {
        float4 va, vb;
        upk2(acc[c4 * 4 + 0], va.x, vb.x);
        upk2(acc[c4 * 4 + 1], va.y, vb.y);
        upk2(acc[c4 * 4 + 2], va.z, vb.z);
        upk2(acc[c4 * 4 + 3], va.w, vb.w);
        *reinterpret_cast<float4*>(pA + c4 * 4) = va;
        *reinterpret_cast<float4*>(pB + c4 * 4) = vb;
    }
}

// ---------------------------------------------------------------------------
// Recurrence: one warp per batch element. lane = g*8+j, g=gate (f,i,u,o), j=unit.
// ---------------------------------------------------------------------------
__global__ void __launch_bounds__(256) lstm_kernel(const float* __restrict__ Wf,
                                                   const float* __restrict__ Wi_,
                                                   const float* __restrict__ Wu,
                                                   const float* __restrict__ Wo,
                                                   const float* __restrict__ Wh2k,
                                                   float* __restrict__ out)
{
    const unsigned FULL = 0xffffffffu;
    int warp = (blockIdx.x * blockDim.x + threadIdx.x) >> 5;
    int lane = threadIdx.x & 31;
    int b = warp;                 // 0..1023
    int g = lane >> 3, j = lane & 7;

    const float* Wsel = (g == 0) ? Wf : (g == 1) ? Wi_ : (g == 2) ? Wu : Wo;
    float Wh[8], Wk[8];
    #pragma unroll
    for (int k = 0; k < 8; k++) {
        Wh[k] = Wsel[(64 + k) * 8 + j];      // h-part rows of the 72x8 gate weight
        Wk[k] = 0.5f * Wh2k[k * 8 + j];      // 0.5 folded into kernel-ansatz weight
    }
    // activation params: gates f,i,o -> sigmoid; gate u -> tanh = 2*sig(2x)-1
    float amul = (g == 2) ? 2.f : 1.f;
    float aneg = (g == 2) ? -2.f : -1.f;
    float aadd = (g == 2) ? -1.f : 0.f;

    float hk[8];
    #pragma unroll
    for (int k = 0; k < 8; k++) hk[k] = 0.f;
    float c = 0.f;

    const float* Pb = g_P + (size_t)b * 40;
    const size_t stride = (size_t)BATCH * 40;
    float px = Pb[lane];           // lane == g*8+j == column index for g<4
    float ps = Pb[32 + j];
    float* outb = out + (size_t)b * HID + j;

    for (int t = 0; t < T_STEPS; t++) {
        // prefetch next step's x-parts (L2-resident)
        float npx = 0.f, nps = 0.f;
        if (t + 1 < T_STEPS) {
            const float* Pn = Pb + (size_t)(t + 1) * stride;
            npx = __ldg(Pn + lane);
            nps = __ldg(Pn + 32 + j);
        }

        // dots against recurrent h
        float pre = px, ka = ps;
        #pragma unroll
        for (int k = 0; k < 8; k++) {
            pre = fmaf(hk[k], Wh[k], pre);
            ka  = fmaf(hk[k], Wk[k], ka);
        }
        float z  = __cosf(pre);
        float ck = __cosf(ka);

        // all-gather z and ck within the 8-lane gate group (independent shfls)
        float zk[8], ckk[8];
        int gb = lane & 24;
        #pragma unroll
        for (int i = 0; i < 8; i++) {
            zk[i]  = __shfl_sync(FULL, z,  gb | i);
            ckk[i] = __shfl_sync(FULL, ck, gb | i);
        }

        // kernel weight w = |prod cos(...)| (tree product; identical on all lanes)
        float w = fabsf(((ckk[0] * ckk[1]) * (ckk[2] * ckk[3])) *
                        ((ckk[4] * ckk[5]) * (ckk[6] * ckk[7])));

        // qlayer output: j==0 -> prod z[1..7]; j>=1 -> z0*...*zj
        int e = (j == 0) ? 7 : j;
        float p = zk[1];
        #pragma unroll
        for (int i = 2; i < 8; i++) if (i <= e) p *= zk[i];
        float res = (j == 0) ? p : zk[0] * p;
        float m = res * w;

        // activation (expf-based, ~1e-6 accurate)
        float ev  = __expf(aneg * m);
        float val = __fdividef(amul, 1.f + ev) + aadd;

        // gather the 4 gate values for this unit
        float fv = __shfl_sync(FULL, val, j);
        float iv = __shfl_sync(FULL, val, 8 + j);
        float gv = __shfl_sync(FULL, val, 16 + j);
        float ov = __shfl_sync(FULL, val, 24 + j);

        c = fmaf(fv, c, iv * gv);
        float tc = __fdividef(2.f, 1.f + __expf(-2.f * c)) - 1.f;
        float hme = ov * tc;

        if (g == 0) outb[(size_t)t * BATCH * HID] = hme;   // outputs[t][b][j]

        // all-gather new h (replicated on every lane)
        #pragma unroll
        for (int k = 0; k < 8; k++) hk[k] = __shfl_sync(FULL, hme, k);

        px = npx; ps = nps;
    }

    if (g == 0) {
        // hx then cx appended after outputs
        out[(size_t)T_STEPS * BATCH * HID + (size_t)b * HID + j] = hk[j];
        out[(size_t)T_STEPS * BATCH * HID + (size_t)BATCH * HID + (size_t)b * HID + j] = c;
    }
}

// ---------------------------------------------------------------------------
// Launch
// ---------------------------------------------------------------------------
extern "C" void kernel_launch(void* const* d_in, const int* in_sizes, int n_in,
                              void* d_out, int out_size)
{
    const float* in[17];
    for (int i = 0; i < 17 && i < n_in; i++) in[i] = (const float*)d_in[i];

    int iIn, iWf, iBf, iTf, iWi, iBi, iTi, iWu, iBu, iTu, iWo, iBo, iTo,
        iWh2k, iBh2k, iWi2k, iBi2k;

    if (in_sizes[0] == T_STEPS * BATCH * IND) {
        iIn = 0; iWh2k = 13; iBh2k = 14; iWi2k = 15; iBi2k = 16;
        if (in_sizes[3] == 576) {
            // reference-signature order: inputs, Wf,bf, Wi,bi, Wu,bu, Wo,bo, th_f..th_o, ...
            iWf = 1; iBf = 2; iWi = 3; iBi = 4; iWu = 5; iBu = 6; iWo = 7; iBo = 8;
            iTf = 9; iTi = 10; iTu = 11; iTo = 12;
        } else {
            // dict-insertion order: inputs, Wf,bf,th_f, Wi,bi,th_i, Wu,bu,th_u, Wo,bo,th_o, ...
            iWf = 1; iBf = 2; iTf = 3; iWi = 4; iBi = 5; iTi = 6;
            iWu = 7; iBu = 8; iTu = 9; iWo = 10; iBo = 11; iTo = 12;
        }
    } else {
        // alphabetical: Wf, Wh2k, Wi, Wi2k, Wo, Wu, bf, bh2k, bi, bi2k, bo, bu, inputs, th_f, th_i, th_o, th_u
        iWf = 0; iWh2k = 1; iWi = 2; iWi2k = 3; iWo = 4; iWu = 5;
        iBf = 6; iBh2k = 7; iBi = 8; iBi2k = 9; iBo = 10; iBu = 11;
        iIn = 12; iTf = 13; iTi = 14; iTo = 15; iTu = 16;
    }

    stage_kernel<<<10, 256>>>(in[iWf], in[iBf], in[iTf],
                              in[iWi], in[iBi], in[iTi],
                              in[iWu], in[iBu], in[iTu],
                              in[iWo], in[iBo], in[iTo],
                              in[iWh2k], in[iBh2k], in[iWi2k], in[iBi2k]);

    xproj_kernel<<<(T_STEPS * BATCH) / 512, 256>>>(in[iIn]);

    lstm_kernel<<<BATCH / 8, 256>>>(in[iWf], in[iWi], in[iWu], in[iWo],
                                    in[iWh2k], (float*)d_out);
}